// round 4
// baseline (speedup 1.0000x reference)
#include <cuda_runtime.h>
#include <math.h>

#define B_ 64
#define T_ 1024
#define I_ 128
#define H_ 512
#define O_ 128
#define GRID0 128
#define NT 512
#define KC 64
#define CHUNK (KC * B_)          // 4096 floats per staged chunk
#define WST0 645                 // 640 + 5 (5 mod 32 -> conflict-free rows)
#define WST1 1029                // 1024 + 5

typedef unsigned long long ull;

// ---- scratch (device globals: allocation-free) ----
__device__ float g_xT[T_ * I_ * B_];      // x transposed: [t][i][b]
__device__ float g_h0buf[2 * H_ * B_];    // layer0 h double buffer
__device__ float g_h1[T_ * H_ * B_];      // layer1 h history: [t][h][b]
__device__ unsigned g_bar_count;
__device__ unsigned g_bar_sense;

// ---- packed f32x2 helpers ----
__device__ __forceinline__ ull pack2(float x) {
    ull r; unsigned u = __float_as_uint(x);
    asm("mov.b64 %0, {%1, %1};" : "=l"(r) : "r"(u));
    return r;
}
__device__ __forceinline__ void ffma2(ull &acc, ull a, ull w) {
    asm("fma.rn.f32x2 %0, %1, %2, %0;" : "+l"(acc) : "l"(a), "l"(w));
}
__device__ __forceinline__ float lo2(ull v) { return __uint_as_float((unsigned)v); }
__device__ __forceinline__ float hi2(ull v) { return __uint_as_float((unsigned)(v >> 32)); }

__device__ __forceinline__ void cp16(float* dst, const float* src) {
    unsigned ds = (unsigned)__cvta_generic_to_shared(dst);
    asm volatile("cp.async.cg.shared.global [%0], [%1], 16;" :: "r"(ds), "l"(src));
}

__device__ __forceinline__ float sigm(float x) {
    return __fdividef(1.f, 1.f + __expf(-x));
}
__device__ __forceinline__ float tanh_(float x) {
    return __fdividef(2.f, 1.f + __expf(-2.f * x)) - 1.f;
}

// ---- grid barrier: atomic arrive + ld.acquire spin (no atomic polling) ----
__device__ __forceinline__ void gridbar(unsigned &sense) {
    __syncthreads();
    if (threadIdx.x == 0) {
        unsigned s = sense ^ 1u;
        sense = s;
        unsigned old;
        asm volatile("atom.release.gpu.global.add.u32 %0, [%1], %2;"
                     : "=r"(old) : "l"(&g_bar_count), "r"(1u));
        if (old == GRID0 - 1u) {
            g_bar_count = 0u;
            asm volatile("st.release.gpu.global.u32 [%0], %1;"
                         :: "l"(&g_bar_sense), "r"(s));
        } else {
            unsigned v;
            do {
                asm volatile("ld.acquire.gpu.global.u32 %0, [%1];"
                             : "=r"(v) : "l"(&g_bar_sense));
            } while (v != s);
        }
    }
    __syncthreads();
}

// ---- stage one KC x 64 chunk of the input vector into smem via cp.async ----
__device__ __forceinline__ void stage_chunk(
    float* __restrict__ dst,
    const float* __restrict__ srcA, const int len0,
    const float* __restrict__ srcB, const int kb)
{
    const int tid = threadIdx.x;
#pragma unroll
    for (int it = 0; it < 2; it++) {
        int v = tid + it * NT;            // 0..1023 float4 slots
        int kk = v >> 4, c4 = (v & 15) << 2;
        int kg = kb + kk;
        float* d = dst + v * 4;
        if (kg < len0)      cp16(d, srcA + kg * B_ + c4);
        else if (srcB)      cp16(d, srcB + (kg - len0) * B_ + c4);
        else                *(float4*)d = make_float4(0.f, 0.f, 0.f, 0.f);
    }
    asm volatile("cp.async.commit_group;");
}

// ---- one LSTM step for this CTA's 4 h-columns (16 gate rows) ----
// thread map: bo = tid&3 (16-batch group), jp = (tid>>2)&7 (row pair), ks = tid>>5 (k-split 16)
__device__ __forceinline__ void lstm_step(
    const float* __restrict__ Ws, const int WST, const int nc,
    const float* __restrict__ bias,
    float* __restrict__ ins, float* __restrict__ red,
    const float* __restrict__ srcA, const int len0,
    const float* __restrict__ srcB,
    float* __restrict__ hout, float &cst, const bool pre0)
{
    const int tid = threadIdx.x;
    const int bo = tid & 3;
    const int jp = (tid >> 2) & 7;
    const int ks = tid >> 5;

    ull a0[8], a1[8];
#pragma unroll
    for (int i = 0; i < 8; i++) { a0[i] = 0ull; a1[i] = 0ull; }

    if (!pre0) stage_chunk(ins, srcA, len0, srcB, 0);

    for (int c = 0; c < nc; c++) {
        if (c + 1 < nc) {
            stage_chunk(ins + ((c + 1) & 1) * CHUNK, srcA, len0, srcB, (c + 1) * KC);
            asm volatile("cp.async.wait_group 1;");
        } else {
            asm volatile("cp.async.wait_group 0;");
        }
        __syncthreads();

        const float* buf = ins + (c & 1) * CHUNK;
        const float* ap  = buf + (ks * 4) * B_ + bo * 16;
        const float* w0p = Ws + (2 * jp) * WST + c * KC + ks * 4;
        const float* w1p = w0p + WST;
#pragma unroll
        for (int kk = 0; kk < 4; kk++) {
            const float* a = ap + kk * B_;
            ulonglong2 A0 = *(const ulonglong2*)(a);
            ulonglong2 A1 = *(const ulonglong2*)(a + 4);
            ulonglong2 A2 = *(const ulonglong2*)(a + 8);
            ulonglong2 A3 = *(const ulonglong2*)(a + 12);
            ull w0 = pack2(w0p[kk]);
            ull w1 = pack2(w1p[kk]);
            ffma2(a0[0], A0.x, w0); ffma2(a0[1], A0.y, w0);
            ffma2(a0[2], A1.x, w0); ffma2(a0[3], A1.y, w0);
            ffma2(a0[4], A2.x, w0); ffma2(a0[5], A2.y, w0);
            ffma2(a0[6], A3.x, w0); ffma2(a0[7], A3.y, w0);
            ffma2(a1[0], A0.x, w1); ffma2(a1[1], A0.y, w1);
            ffma2(a1[2], A1.x, w1); ffma2(a1[3], A1.y, w1);
            ffma2(a1[4], A2.x, w1); ffma2(a1[5], A2.y, w1);
            ffma2(a1[6], A3.x, w1); ffma2(a1[7], A3.y, w1);
        }
        __syncthreads();
    }

    // k-split reduction through smem (once per step)
    {
        int rb = ks * 1024 + (2 * jp) * B_ + bo * 16;
#pragma unroll
        for (int p = 0; p < 8; p++) *(ull*)(red + rb + 2 * p) = a0[p];
        rb += B_;
#pragma unroll
        for (int p = 0; p < 8; p++) *(ull*)(red + rb + 2 * p) = a1[p];
    }
    __syncthreads();

    if (tid < 256) {
        int c4 = tid >> 6;
        int b  = tid & 63;
        float xi = bias[c4], xf = bias[4 + c4], xg = bias[8 + c4], xo = bias[12 + c4];
#pragma unroll
        for (int s = 0; s < 16; s++) {
            const float* r = red + s * 1024 + b;
            xi += r[(0  + c4) * B_];
            xf += r[(4  + c4) * B_];
            xg += r[(8  + c4) * B_];
            xo += r[(12 + c4) * B_];
        }
        float ii = sigm(xi), ff = sigm(xf), gg = tanh_(xg), oo = sigm(xo);
        cst = ff * cst + ii * gg;
        hout[c4 * B_ + b] = oo * tanh_(cst);
    }
}

// ---------------------------------------------------------------------------
// Mega kernel: transpose + both LSTM layers (pipelined) + FC, one launch.
__global__ void __launch_bounds__(NT, 1) mega_kernel(
    const float* __restrict__ x,
    const float* __restrict__ W_ih0, const float* __restrict__ W_hh0,
    const float* __restrict__ b_ih0, const float* __restrict__ b_hh0,
    const float* __restrict__ W_ih1, const float* __restrict__ W_hh1,
    const float* __restrict__ b_ih1, const float* __restrict__ b_hh1,
    const float* __restrict__ Wfc,  const float* __restrict__ bfc,
    float* __restrict__ out)
{
    extern __shared__ float sm[];
    float* Ws0   = sm;                      // 16 * 645
    float* Ws1   = Ws0 + 16 * WST0;         // 16 * 1029
    float* bias0 = Ws1 + 16 * WST1;         // 16
    float* bias1 = bias0 + 16;              // 16
    float* ins   = bias1 + 16;              // 2 * CHUNK
    float* red   = ins + 2 * CHUNK;         // 16 * 16 * 64 = 16384

    const int tid = threadIdx.x;
    const int hj0 = blockIdx.x * 4;

    unsigned sense = 0;
    if (tid == 0) sense = *(volatile unsigned*)&g_bar_sense;

    // ---- weight slices: local row r = gate*4 + c <-> global row gate*512 + hj0 + c
    for (int idx = tid; idx < 16 * 640; idx += NT) {
        int r = idx / 640, k = idx - r * 640;
        int grow = (r >> 2) * H_ + hj0 + (r & 3);
        Ws0[r * WST0 + k] = (k < I_) ? W_ih0[grow * I_ + k]
                                     : W_hh0[grow * H_ + (k - I_)];
    }
    for (int idx = tid; idx < 16 * 1024; idx += NT) {
        int r = idx >> 10, k = idx & 1023;
        int grow = (r >> 2) * H_ + hj0 + (r & 3);
        Ws1[r * WST1 + k] = (k < H_) ? W_ih1[grow * H_ + k]
                                     : W_hh1[grow * H_ + (k - H_)];
    }
    if (tid < 16) {
        int grow = (tid >> 2) * H_ + hj0 + (tid & 3);
        bias0[tid] = b_ih0[grow] + b_hh0[grow];
        bias1[tid] = b_ih1[grow] + b_hh1[grow];
    }

    // ---- transpose phase: x[b][t][i] -> g_xT[t][i][b] (tile in red region)
    {
        float (*tile)[I_ + 1] = (float (*)[I_ + 1])red;   // 64 x 129
        for (int t = blockIdx.x; t < T_; t += GRID0) {
            __syncthreads();
            for (int idx = tid; idx < B_ * I_; idx += NT) {
                int b = idx >> 7, i = idx & 127;
                tile[b][i] = x[(b * T_ + t) * I_ + i];
            }
            __syncthreads();
            for (int idx = tid; idx < B_ * I_; idx += NT) {
                int b = idx & 63, i = idx >> 6;
                g_xT[t * I_ * B_ + i * B_ + b] = tile[b][i];
            }
        }
    }
    gridbar(sense);

    // ---- main pipelined loop: layer0 at t=k, layer1 at s=k-1
    float c0st = 0.f, c1st = 0.f;
    for (int k = 0; k <= T_; ++k) {
        if (k < T_) {
            const float* srcB = (k > 0) ? (g_h0buf + ((k - 1) & 1) * H_ * B_)
                                        : (const float*)0;
            lstm_step(Ws0, WST0, 640 / KC, bias0, ins, red,
                      g_xT + k * I_ * B_, I_, srcB,
                      g_h0buf + (k & 1) * H_ * B_ + hj0 * B_, c0st, k > 0);
        }
        if (k >= 1) {
            int s = k - 1;
            const float* srcB = (s > 0) ? (g_h1 + (s - 1) * H_ * B_)
                                        : (const float*)0;
            lstm_step(Ws1, WST1, 1024 / KC, bias1, ins, red,
                      g_h0buf + (s & 1) * H_ * B_, H_, srcB,
                      g_h1 + s * H_ * B_ + hj0 * B_, c1st, false);
        }
        // prefetch next layer0 chunk 0 (pure x, static data) across the barrier
        if (k + 1 < T_) {
            stage_chunk(ins, g_xT + (k + 1) * I_ * B_, I_, (const float*)0, 0);
        }
        gridbar(sense);
    }

    // ---- FC phase: out[b][t][o] = sum_h h1[t][h][b] * Wfc[o][h] + bfc[o]
    {
        float* w_s = red;                 // 128 * 65 = 8320
        float* h_s = red + 128 * 65;      // 64 * 64  = 4096
        const int o  = tid & 127;
        const int bq = tid >> 7;          // 0..3 -> batch 16bq..16bq+15
        const float bfc_r = __ldg(&bfc[o]);

        for (int t = blockIdx.x; t < T_; t += GRID0) {
            ull acc[8];
#pragma unroll
            for (int p = 0; p < 8; p++) acc[p] = 0ull;

            for (int kb = 0; kb < H_; kb += 64) {
                __syncthreads();
                for (int idx = tid; idx < O_ * 64; idx += NT) {
                    int oo = idx >> 6, kk = idx & 63;
                    w_s[oo * 65 + kk] = Wfc[oo * H_ + kb + kk];
                }
                for (int idx = tid; idx < 64 * B_; idx += NT) {
                    h_s[idx] = g_h1[(t * H_ + kb) * B_ + idx];
                }
                __syncthreads();
#pragma unroll 8
                for (int kk = 0; kk < 64; kk++) {
                    const float* a = h_s + kk * B_ + bq * 16;
                    ulonglong2 A0 = *(const ulonglong2*)(a);
                    ulonglong2 A1 = *(const ulonglong2*)(a + 4);
                    ulonglong2 A2 = *(const ulonglong2*)(a + 8);
                    ulonglong2 A3 = *(const ulonglong2*)(a + 12);
                    ull w = pack2(w_s[o * 65 + kk]);
                    ffma2(acc[0], A0.x, w); ffma2(acc[1], A0.y, w);
                    ffma2(acc[2], A1.x, w); ffma2(acc[3], A1.y, w);
                    ffma2(acc[4], A2.x, w); ffma2(acc[5], A2.y, w);
                    ffma2(acc[6], A3.x, w); ffma2(acc[7], A3.y, w);
                }
            }
#pragma unroll
            for (int p = 0; p < 8; p++) {
                int b = bq * 16 + 2 * p;
                out[(b * T_ + t) * O_ + o]       = lo2(acc[p]) + bfc_r;
                out[((b + 1) * T_ + t) * O_ + o] = hi2(acc[p]) + bfc_r;
            }
        }
    }
}

// ---------------------------------------------------------------------------
extern "C" void kernel_launch(void* const* d_in, const int* in_sizes, int n_in,
                              void* d_out, int out_size) {
    const float* x     = (const float*)d_in[0];
    const float* W_ih0 = (const float*)d_in[1];
    const float* W_hh0 = (const float*)d_in[2];
    const float* b_ih0 = (const float*)d_in[3];
    const float* b_hh0 = (const float*)d_in[4];
    const float* W_ih1 = (const float*)d_in[5];
    const float* W_hh1 = (const float*)d_in[6];
    const float* b_ih1 = (const float*)d_in[7];
    const float* b_hh1 = (const float*)d_in[8];
    const float* W_fc  = (const float*)d_in[9];
    const float* b_fc  = (const float*)d_in[10];
    float* out = (float*)d_out;

    size_t smem = (size_t)(16 * WST0 + 16 * WST1 + 32 + 2 * CHUNK + 16384) * sizeof(float);
    cudaFuncSetAttribute(mega_kernel, cudaFuncAttributeMaxDynamicSharedMemorySize, (int)smem);

    mega_kernel<<<GRID0, NT, smem>>>(x, W_ih0, W_hh0, b_ih0, b_hh0,
                                     W_ih1, W_hh1, b_ih1, b_hh1,
                                     W_fc, b_fc, out);
}

// round 5
// speedup vs baseline: 1.0013x; 1.0013x over previous
#include <cuda_runtime.h>
#include <math.h>

#define B_ 64
#define T_ 1024
#define I_ 128
#define H_ 512
#define O_ 128
#define GRID0 128
#define NT 512
#define KC 64
#define CHUNK (KC * B_)          // 4096 floats per staged chunk
#define WST0 645                 // 640 + 5 (5 mod 32 -> conflict-free rows)
#define WST1 1029                // 1024 + 5

typedef unsigned long long ull;

// ---- scratch (device globals: allocation-free) ----
__device__ float g_xT[T_ * I_ * B_];      // x transposed: [t][i][b]
__device__ float g_h0buf[2 * H_ * B_];    // layer0 h double buffer
__device__ float g_h1[T_ * H_ * B_];      // layer1 h history: [t][h][b]
__device__ unsigned g_bar_count;
__device__ unsigned g_bar_sense;

// ---- packed f32x2 helpers ----
__device__ __forceinline__ ull pack2(float x) {
    ull r; unsigned u = __float_as_uint(x);
    asm("mov.b64 %0, {%1, %1};" : "=l"(r) : "r"(u));
    return r;
}
__device__ __forceinline__ void ffma2(ull &acc, ull a, ull w) {
    asm("fma.rn.f32x2 %0, %1, %2, %0;" : "+l"(acc) : "l"(a), "l"(w));
}
__device__ __forceinline__ float lo2(ull v) { return __uint_as_float((unsigned)v); }
__device__ __forceinline__ float hi2(ull v) { return __uint_as_float((unsigned)(v >> 32)); }

__device__ __forceinline__ void cp16(float* dst, const float* src) {
    unsigned ds = (unsigned)__cvta_generic_to_shared(dst);
    asm volatile("cp.async.cg.shared.global [%0], [%1], 16;" :: "r"(ds), "l"(src));
}

__device__ __forceinline__ float sigm(float x) {
    return __fdividef(1.f, 1.f + __expf(-x));
}
__device__ __forceinline__ float tanh_(float x) {
    return __fdividef(2.f, 1.f + __expf(-2.f * x)) - 1.f;
}

// ---- grid barrier: atomic arrive + ld.acquire spin (no atomic polling) ----
__device__ __forceinline__ void gridbar(unsigned &sense) {
    __syncthreads();
    if (threadIdx.x == 0) {
        unsigned s = sense ^ 1u;
        sense = s;
        unsigned old;
        asm volatile("atom.release.gpu.global.add.u32 %0, [%1], %2;"
                     : "=r"(old) : "l"(&g_bar_count), "r"(1u));
        if (old == GRID0 - 1u) {
            g_bar_count = 0u;
            asm volatile("st.release.gpu.global.u32 [%0], %1;"
                         :: "l"(&g_bar_sense), "r"(s));
        } else {
            unsigned v;
            do {
                asm volatile("ld.acquire.gpu.global.u32 %0, [%1];"
                             : "=r"(v) : "l"(&g_bar_sense));
            } while (v != s);
        }
    }
    __syncthreads();
}

// ---- stage one KC x 64 chunk of the input vector into smem via cp.async ----
__device__ __forceinline__ void stage_chunk(
    float* __restrict__ dst,
    const float* __restrict__ srcA, const int len0,
    const float* __restrict__ srcB, const int kb)
{
    const int tid = threadIdx.x;
#pragma unroll
    for (int it = 0; it < 2; it++) {
        int v = tid + it * NT;            // 0..1023 float4 slots
        int kk = v >> 4, c4 = (v & 15) << 2;
        int kg = kb + kk;
        float* d = dst + v * 4;
        if (kg < len0)      cp16(d, srcA + kg * B_ + c4);
        else if (srcB)      cp16(d, srcB + (kg - len0) * B_ + c4);
        else                *(float4*)d = make_float4(0.f, 0.f, 0.f, 0.f);
    }
    asm volatile("cp.async.commit_group;");
}

// ---- one LSTM step for this CTA's 4 h-columns (16 gate rows) ----
// thread map: bo = tid&3 (16-batch group), jp = (tid>>2)&7 (row pair), ks = tid>>5 (k-split 16)
__device__ __forceinline__ void lstm_step(
    const float* __restrict__ Ws, const int WST, const int nc,
    const float* __restrict__ bias,
    float* __restrict__ ins, float* __restrict__ red,
    const float* __restrict__ srcA, const int len0,
    const float* __restrict__ srcB,
    float* __restrict__ hout, float &cst, const bool pre0)
{
    const int tid = threadIdx.x;
    const int bo = tid & 3;
    const int jp = (tid >> 2) & 7;
    const int ks = tid >> 5;

    ull a0[8], a1[8];
#pragma unroll
    for (int i = 0; i < 8; i++) { a0[i] = 0ull; a1[i] = 0ull; }

    if (!pre0) stage_chunk(ins, srcA, len0, srcB, 0);

    for (int c = 0; c < nc; c++) {
        if (c + 1 < nc) {
            stage_chunk(ins + ((c + 1) & 1) * CHUNK, srcA, len0, srcB, (c + 1) * KC);
            asm volatile("cp.async.wait_group 1;");
        } else {
            asm volatile("cp.async.wait_group 0;");
        }
        __syncthreads();

        const float* buf = ins + (c & 1) * CHUNK;
        const float* ap  = buf + (ks * 4) * B_ + bo * 16;
        const float* w0p = Ws + (2 * jp) * WST + c * KC + ks * 4;
        const float* w1p = w0p + WST;
#pragma unroll
        for (int kk = 0; kk < 4; kk++) {
            const float* a = ap + kk * B_;
            ulonglong2 A0 = *(const ulonglong2*)(a);
            ulonglong2 A1 = *(const ulonglong2*)(a + 4);
            ulonglong2 A2 = *(const ulonglong2*)(a + 8);
            ulonglong2 A3 = *(const ulonglong2*)(a + 12);
            ull w0 = pack2(w0p[kk]);
            ull w1 = pack2(w1p[kk]);
            ffma2(a0[0], A0.x, w0); ffma2(a0[1], A0.y, w0);
            ffma2(a0[2], A1.x, w0); ffma2(a0[3], A1.y, w0);
            ffma2(a0[4], A2.x, w0); ffma2(a0[5], A2.y, w0);
            ffma2(a0[6], A3.x, w0); ffma2(a0[7], A3.y, w0);
            ffma2(a1[0], A0.x, w1); ffma2(a1[1], A0.y, w1);
            ffma2(a1[2], A1.x, w1); ffma2(a1[3], A1.y, w1);
            ffma2(a1[4], A2.x, w1); ffma2(a1[5], A2.y, w1);
            ffma2(a1[6], A3.x, w1); ffma2(a1[7], A3.y, w1);
        }
        __syncthreads();
    }

    // k-split reduction through smem (once per step)
    {
        int rb = ks * 1024 + (2 * jp) * B_ + bo * 16;
#pragma unroll
        for (int p = 0; p < 8; p++) *(ull*)(red + rb + 2 * p) = a0[p];
        rb += B_;
#pragma unroll
        for (int p = 0; p < 8; p++) *(ull*)(red + rb + 2 * p) = a1[p];
    }
    __syncthreads();

    if (tid < 256) {
        int c4 = tid >> 6;
        int b  = tid & 63;
        float xi = bias[c4], xf = bias[4 + c4], xg = bias[8 + c4], xo = bias[12 + c4];
#pragma unroll
        for (int s = 0; s < 16; s++) {
            const float* r = red + s * 1024 + b;
            xi += r[(0  + c4) * B_];
            xf += r[(4  + c4) * B_];
            xg += r[(8  + c4) * B_];
            xo += r[(12 + c4) * B_];
        }
        float ii = sigm(xi), ff = sigm(xf), gg = tanh_(xg), oo = sigm(xo);
        cst = ff * cst + ii * gg;
        hout[c4 * B_ + b] = oo * tanh_(cst);
    }
}

// ---------------------------------------------------------------------------
// Mega kernel: transpose + both LSTM layers (pipelined) + FC, one launch.
__global__ void __launch_bounds__(NT, 1) mega_kernel(
    const float* __restrict__ x,
    const float* __restrict__ W_ih0, const float* __restrict__ W_hh0,
    const float* __restrict__ b_ih0, const float* __restrict__ b_hh0,
    const float* __restrict__ W_ih1, const float* __restrict__ W_hh1,
    const float* __restrict__ b_ih1, const float* __restrict__ b_hh1,
    const float* __restrict__ Wfc,  const float* __restrict__ bfc,
    float* __restrict__ out)
{
    extern __shared__ float sm[];
    float* Ws0   = sm;                      // 16 * 645
    float* Ws1   = Ws0 + 16 * WST0;         // 16 * 1029
    float* bias0 = Ws1 + 16 * WST1;         // 16
    float* bias1 = bias0 + 16;              // 16
    float* ins   = bias1 + 16;              // 2 * CHUNK
    float* red   = ins + 2 * CHUNK;         // 16 * 16 * 64 = 16384

    const int tid = threadIdx.x;
    const int hj0 = blockIdx.x * 4;

    unsigned sense = 0;
    if (tid == 0) sense = *(volatile unsigned*)&g_bar_sense;

    // ---- weight slices: local row r = gate*4 + c <-> global row gate*512 + hj0 + c
    for (int idx = tid; idx < 16 * 640; idx += NT) {
        int r = idx / 640, k = idx - r * 640;
        int grow = (r >> 2) * H_ + hj0 + (r & 3);
        Ws0[r * WST0 + k] = (k < I_) ? W_ih0[grow * I_ + k]
                                     : W_hh0[grow * H_ + (k - I_)];
    }
    for (int idx = tid; idx < 16 * 1024; idx += NT) {
        int r = idx >> 10, k = idx & 1023;
        int grow = (r >> 2) * H_ + hj0 + (r & 3);
        Ws1[r * WST1 + k] = (k < H_) ? W_ih1[grow * H_ + k]
                                     : W_hh1[grow * H_ + (k - H_)];
    }
    if (tid < 16) {
        int grow = (tid >> 2) * H_ + hj0 + (tid & 3);
        bias0[tid] = b_ih0[grow] + b_hh0[grow];
        bias1[tid] = b_ih1[grow] + b_hh1[grow];
    }

    // ---- transpose phase: x[b][t][i] -> g_xT[t][i][b] (tile in red region)
    {
        float (*tile)[I_ + 1] = (float (*)[I_ + 1])red;   // 64 x 129
        for (int t = blockIdx.x; t < T_; t += GRID0) {
            __syncthreads();
            for (int idx = tid; idx < B_ * I_; idx += NT) {
                int b = idx >> 7, i = idx & 127;
                tile[b][i] = x[(b * T_ + t) * I_ + i];
            }
            __syncthreads();
            for (int idx = tid; idx < B_ * I_; idx += NT) {
                int b = idx & 63, i = idx >> 6;
                g_xT[t * I_ * B_ + i * B_ + b] = tile[b][i];
            }
        }
    }
    gridbar(sense);

    // ---- main pipelined loop: layer0 at t=k, layer1 at s=k-1
    float c0st = 0.f, c1st = 0.f;
    for (int k = 0; k <= T_; ++k) {
        if (k < T_) {
            const float* srcB = (k > 0) ? (g_h0buf + ((k - 1) & 1) * H_ * B_)
                                        : (const float*)0;
            lstm_step(Ws0, WST0, 640 / KC, bias0, ins, red,
                      g_xT + k * I_ * B_, I_, srcB,
                      g_h0buf + (k & 1) * H_ * B_ + hj0 * B_, c0st, k > 0);
        }
        if (k >= 1) {
            int s = k - 1;
            const float* srcB = (s > 0) ? (g_h1 + (s - 1) * H_ * B_)
                                        : (const float*)0;
            lstm_step(Ws1, WST1, 1024 / KC, bias1, ins, red,
                      g_h0buf + (s & 1) * H_ * B_, H_, srcB,
                      g_h1 + s * H_ * B_ + hj0 * B_, c1st, false);
        }
        // prefetch next layer0 chunk 0 (pure x, static data) across the barrier
        if (k + 1 < T_) {
            stage_chunk(ins, g_xT + (k + 1) * I_ * B_, I_, (const float*)0, 0);
        }
        gridbar(sense);
    }

    // ---- FC phase: out[b][t][o] = sum_h h1[t][h][b] * Wfc[o][h] + bfc[o]
    {
        float* w_s = red;                 // 128 * 65 = 8320
        float* h_s = red + 128 * 65;      // 64 * 64  = 4096
        const int o  = tid & 127;
        const int bq = tid >> 7;          // 0..3 -> batch 16bq..16bq+15
        const float bfc_r = __ldg(&bfc[o]);

        for (int t = blockIdx.x; t < T_; t += GRID0) {
            ull acc[8];
#pragma unroll
            for (int p = 0; p < 8; p++) acc[p] = 0ull;

            for (int kb = 0; kb < H_; kb += 64) {
                __syncthreads();
                for (int idx = tid; idx < O_ * 64; idx += NT) {
                    int oo = idx >> 6, kk = idx & 63;
                    w_s[oo * 65 + kk] = Wfc[oo * H_ + kb + kk];
                }
                for (int idx = tid; idx < 64 * B_; idx += NT) {
                    h_s[idx] = g_h1[(t * H_ + kb) * B_ + idx];
                }
                __syncthreads();
#pragma unroll 8
                for (int kk = 0; kk < 64; kk++) {
                    const float* a = h_s + kk * B_ + bq * 16;
                    ulonglong2 A0 = *(const ulonglong2*)(a);
                    ulonglong2 A1 = *(const ulonglong2*)(a + 4);
                    ulonglong2 A2 = *(const ulonglong2*)(a + 8);
                    ulonglong2 A3 = *(const ulonglong2*)(a + 12);
                    ull w = pack2(w_s[o * 65 + kk]);
                    ffma2(acc[0], A0.x, w); ffma2(acc[1], A0.y, w);
                    ffma2(acc[2], A1.x, w); ffma2(acc[3], A1.y, w);
                    ffma2(acc[4], A2.x, w); ffma2(acc[5], A2.y, w);
                    ffma2(acc[6], A3.x, w); ffma2(acc[7], A3.y, w);
                }
            }
#pragma unroll
            for (int p = 0; p < 8; p++) {
                int b = bq * 16 + 2 * p;
                out[(b * T_ + t) * O_ + o]       = lo2(acc[p]) + bfc_r;
                out[((b + 1) * T_ + t) * O_ + o] = hi2(acc[p]) + bfc_r;
            }
        }
    }
}

// ---------------------------------------------------------------------------
extern "C" void kernel_launch(void* const* d_in, const int* in_sizes, int n_in,
                              void* d_out, int out_size) {
    const float* x     = (const float*)d_in[0];
    const float* W_ih0 = (const float*)d_in[1];
    const float* W_hh0 = (const float*)d_in[2];
    const float* b_ih0 = (const float*)d_in[3];
    const float* b_hh0 = (const float*)d_in[4];
    const float* W_ih1 = (const float*)d_in[5];
    const float* W_hh1 = (const float*)d_in[6];
    const float* b_ih1 = (const float*)d_in[7];
    const float* b_hh1 = (const float*)d_in[8];
    const float* W_fc  = (const float*)d_in[9];
    const float* b_fc  = (const float*)d_in[10];
    float* out = (float*)d_out;

    size_t smem = (size_t)(16 * WST0 + 16 * WST1 + 32 + 2 * CHUNK + 16384) * sizeof(float);
    cudaFuncSetAttribute(mega_kernel, cudaFuncAttributeMaxDynamicSharedMemorySize, (int)smem);

    mega_kernel<<<GRID0, NT, smem>>>(x, W_ih0, W_hh0, b_ih0, b_hh0,
                                     W_ih1, W_hh1, b_ih1, b_hh1,
                                     W_fc, b_fc, out);
}